// round 16
// baseline (speedup 1.0000x reference)
#include <cuda_runtime.h>
#include <cstdint>
#include <math.h>

// Problem shape (fixed)
constexpr int B_ = 4, T_ = 2048, C_ = 1024, H_ = 16, D_ = 64;
constexpr int M_ = B_ * T_;  // 8192

// Scratch (allocations are forbidden; use __device__ globals)
__device__ float g_q[M_ * C_];
__device__ float g_k[M_ * C_];
__device__ float g_v[M_ * C_];
__device__ float g_y[M_ * C_];
__device__ float g_x[M_ * C_];        // tf32-rounded x
__device__ float g_w[4 * C_ * C_];    // tf32-rounded wq|wk|wv|wp

// ---------------------------------------------------------------------------
// helpers
// ---------------------------------------------------------------------------
__device__ __forceinline__ uint32_t smem_u32(const void* p) {
    uint32_t a;
    asm("{ .reg .u64 t; cvta.to.shared.u64 t, %1; cvt.u32.u64 %0, t; }"
        : "=r"(a) : "l"(p));
    return a;
}
__device__ __forceinline__ uint32_t tf32r(float x) {
    uint32_t u;
    asm("cvt.rna.tf32.f32 %0, %1;" : "=r"(u) : "f"(x));
    return u;
}
__device__ __forceinline__ void mma_u(float* c, uint32_t a0, uint32_t a1,
                                      uint32_t a2, uint32_t a3,
                                      uint32_t b0, uint32_t b1) {
    asm volatile(
        "mma.sync.aligned.m16n8k8.row.col.f32.tf32.tf32.f32 "
        "{%0,%1,%2,%3}, {%4,%5,%6,%7}, {%8,%9}, {%0,%1,%2,%3};"
        : "+f"(c[0]), "+f"(c[1]), "+f"(c[2]), "+f"(c[3])
        : "r"(a0), "r"(a1), "r"(a2), "r"(a3), "r"(b0), "r"(b1));
}
#define CP_ASYNC16(dst, src) \
    asm volatile("cp.async.cg.shared.global [%0], [%1], 16;" \
                 :: "r"(dst), "l"(src) : "memory")
#define CP_COMMIT() asm volatile("cp.async.commit_group;" ::: "memory")
#define CP_WAIT0()  asm volatile("cp.async.wait_group 0;" ::: "memory")

// ---------------------------------------------------------------------------
// Pre-round x and the four weight matrices to tf32 (RNA) in gmem.
// ---------------------------------------------------------------------------
__global__ __launch_bounds__(256) void round_tf32(
    const float* __restrict__ x,
    const float* __restrict__ wq, const float* __restrict__ wk,
    const float* __restrict__ wv, const float* __restrict__ wp,
    float* __restrict__ gx, float* __restrict__ gw)
{
    const int XF = M_ * C_ / 4;
    const int WF = C_ * C_ / 4;
    int i4 = blockIdx.x * 256 + threadIdx.x;
    const float4* src;
    float4* dst;
    if (i4 < XF) {
        src = reinterpret_cast<const float4*>(x);
        dst = reinterpret_cast<float4*>(gx);
    } else {
        int j = i4 - XF;
        int w = j / WF;
        i4 = j - w * WF;
        const float* ws = (w == 0) ? wq : (w == 1) ? wk : (w == 2) ? wv : wp;
        src = reinterpret_cast<const float4*>(ws);
        dst = reinterpret_cast<float4*>(gw + (size_t)w * C_ * C_);
    }
    float4 t = src[i4];
    uint4 u;
    u.x = tf32r(t.x); u.y = tf32r(t.y); u.z = tf32r(t.z); u.w = tf32r(t.w);
    *reinterpret_cast<uint4*>(&dst[i4]) = u;
}

// ---------------------------------------------------------------------------
// GEMM via mma.sync tf32: CTA 256x128, BK=32, cp.async 2-stage, register
// double-buffered fragments (overlap LDS with MMA). blockIdx.z selects
// (W, bias, out); z == round_z outputs stored tf32-rounded.
// ---------------------------------------------------------------------------
constexpr int BK = 32, LDSG = 40;
constexpr int A_STF = 256 * LDSG;
constexpr int B_STF = 128 * LDSG;
constexpr int GEMM_SMEM = (2 * A_STF + 2 * B_STF) * 4;  // 122880 B

__global__ __launch_bounds__(256, 1) void gemm_mma(
    const float* __restrict__ A, const float* __restrict__ Wb,
    const float* __restrict__ bias0, const float* __restrict__ bias1,
    const float* __restrict__ bias2,
    float* __restrict__ out0, float* __restrict__ out1,
    float* __restrict__ out2, int round_z)
{
    extern __shared__ __align__(16) float smg[];
    const uint32_t sbase = smem_u32(smg);
    const int tid = threadIdx.x;
    const int lane = tid & 31, wid = tid >> 5;
    const int warp_m = wid & 3, warp_n = wid >> 2;        // 4 x 2
    const int row0 = blockIdx.y * 256, col0 = blockIdx.x * 128;
    const int r = lane >> 2, kc = lane & 3;
    const int z = blockIdx.z;

    const float* W = Wb + (size_t)z * C_ * C_;
    const float* bias = (z == 0) ? bias0 : (z == 1) ? bias1 : bias2;
    float* out = (z == 0) ? out0 : (z == 1) ? out1 : out2;
    const bool rnd = (z == round_z);

    float acc[4][8][4];
#pragma unroll
    for (int i = 0; i < 4; i++)
#pragma unroll
        for (int j = 0; j < 8; j++)
#pragma unroll
            for (int q = 0; q < 4; q++) acc[i][j][q] = 0.f;

    const int lrow = tid >> 3, lc4 = (tid & 7) * 4;
    const float* gA = &A[(size_t)(row0 + lrow) * C_ + lc4];
    const float* gW = &W[(size_t)(col0 + lrow) * C_ + lc4];
    const uint32_t soff = (uint32_t)(lrow * LDSG + lc4) * 4;

    auto issue = [&](int c) {
        const int k0 = c * BK;
        const uint32_t sa = sbase + (uint32_t)((c & 1) * A_STF) * 4 + soff;
        const uint32_t sb = sbase + (uint32_t)(2 * A_STF + (c & 1) * B_STF) * 4 + soff;
#pragma unroll
        for (int it = 0; it < 8; it++)
            CP_ASYNC16(sa + (uint32_t)(it * 32 * LDSG) * 4,
                       gA + (size_t)it * 32 * C_ + k0);
#pragma unroll
        for (int it = 0; it < 4; it++)
            CP_ASYNC16(sb + (uint32_t)(it * 32 * LDSG) * 4,
                       gW + (size_t)it * 32 * C_ + k0);
        CP_COMMIT();
    };

    issue(0);

    const int NCH = C_ / BK;  // 32
    for (int c = 0; c < NCH; c++) {
        CP_WAIT0();
        __syncthreads();
        if (c + 1 < NCH) issue(c + 1);

        const float* as = smg + (c & 1) * A_STF;
        const float* bs = smg + 2 * A_STF + (c & 1) * B_STF;
        const int ar = warp_m * 64 + r;
        const int br = warp_n * 64 + r;

        // register double-buffered fragments over kk
        uint2 fa01[2][4], fa23[2][4], fb[2][8];
#define G_LOAD(kkv, bf)                                                      \
        {                                                                    \
            const int ko = 8 * (kkv) + 2 * kc;                               \
            _Pragma("unroll")                                                \
            for (int mt = 0; mt < 4; mt++) {                                 \
                fa01[bf][mt] = *reinterpret_cast<const uint2*>(              \
                    &as[(ar + mt * 16) * LDSG + ko]);                        \
                fa23[bf][mt] = *reinterpret_cast<const uint2*>(              \
                    &as[(ar + mt * 16 + 8) * LDSG + ko]);                    \
            }                                                                \
            _Pragma("unroll")                                                \
            for (int nt = 0; nt < 8; nt++)                                   \
                fb[bf][nt] = *reinterpret_cast<const uint2*>(                \
                    &bs[(br + nt * 8) * LDSG + ko]);                         \
        }
        G_LOAD(0, 0)
#pragma unroll
        for (int kk = 0; kk < 4; kk++) {
            const int bf = kk & 1;
            if (kk < 3) G_LOAD(kk + 1, bf ^ 1)
#pragma unroll
            for (int nt = 0; nt < 8; nt++)
#pragma unroll
                for (int mt = 0; mt < 4; mt++)
                    mma_u(acc[mt][nt], fa01[bf][mt].x, fa23[bf][mt].x,
                          fa01[bf][mt].y, fa23[bf][mt].y,
                          fb[bf][nt].x, fb[bf][nt].y);
        }
#undef G_LOAD
    }

    const int orow = row0 + warp_m * 64 + r;
    const int ocol = col0 + warp_n * 64 + 2 * kc;
#pragma unroll
    for (int nt = 0; nt < 8; nt++) {
        const int cg = ocol + nt * 8;
        const float b0 = bias[cg], b1 = bias[cg + 1];
#pragma unroll
        for (int mt = 0; mt < 4; mt++) {
            float2 v0 = make_float2(acc[mt][nt][0] + b0, acc[mt][nt][1] + b1);
            float2 v1 = make_float2(acc[mt][nt][2] + b0, acc[mt][nt][3] + b1);
            if (rnd) {
                v0.x = __uint_as_float(tf32r(v0.x));
                v0.y = __uint_as_float(tf32r(v0.y));
                v1.x = __uint_as_float(tf32r(v1.x));
                v1.y = __uint_as_float(tf32r(v1.y));
            }
            *reinterpret_cast<float2*>(&out[(size_t)(orow + mt * 16) * C_ + cg]) = v0;
            *reinterpret_cast<float2*>(&out[(size_t)(orow + mt * 16 + 8) * C_ + cg]) = v1;
        }
    }
}

// ---------------------------------------------------------------------------
// RoPE in place on q and k; stores tf32-rounded (attention consumes raw).
// ---------------------------------------------------------------------------
__global__ __launch_bounds__(256) void rope_kernel(float* __restrict__ q,
                                                   float* __restrict__ k)
{
    int idx = blockIdx.x * 256 + threadIdx.x;
    int half = idx & 31;
    int h = (idx >> 5) & 15;
    int t = (idx >> 9) & 2047;
    int b = idx >> 20;

    float alpha = exp2f(-(float)half * 0.41524101186092029f);
    float ang = (float)t * alpha;
    float c = cosf(ang), s = sinf(ang);

    size_t off = ((size_t)b * T_ + t) * C_ + h * D_ + half;
    float xr = q[off], xi = q[off + 32];
    reinterpret_cast<uint32_t*>(q)[off]      = tf32r(xr * c - xi * s);
    reinterpret_cast<uint32_t*>(q)[off + 32] = tf32r(xr * s + xi * c);
    xr = k[off]; xi = k[off + 32];
    reinterpret_cast<uint32_t*>(k)[off]      = tf32r(xr * c - xi * s);
    reinterpret_cast<uint32_t*>(k)[off + 32] = tf32r(xr * s + xi * c);
}

// ---------------------------------------------------------------------------
// Tensor-core flash attention v3 (causal, tf32 mma, online softmax).
// CTA: 128 queries, 4 warps (128 threads); warp owns 32 q rows (mt in {0,1}).
// K/V cp.async double-buffered; register double-buffered fragments (overlap
// LDS with MMA). PV: P as A-operand from registers, row-major V as B-operand.
// ---------------------------------------------------------------------------
constexpr int LDQ = 72;                       // Q,K smem stride (floats)
constexpr int LDV = 68;                       // V smem stride (floats)
constexpr int QF = 128 * LDQ;                 // 9216
constexpr int KF = 64 * LDQ;                  // 4608 per buffer
constexpr int VF = 64 * LDV;                  // 4352 per buffer
constexpr int ATTN_SMEM3 = (QF + 2 * KF + 2 * VF) * 4;  // 108544 B

__global__ __launch_bounds__(128, 2) void attn_mma(
    const float* __restrict__ q, const float* __restrict__ k,
    const float* __restrict__ v, float* __restrict__ y)
{
    extern __shared__ __align__(16) float sma[];
    float* Qs = sma;                       // [128][72]
    float* Ksb = sma + QF;                 // [2][64][72]
    float* Vsb = sma + QF + 2 * KF;        // [2][64][68]
    const uint32_t sbase = smem_u32(sma);

    const int tid = threadIdx.x;
    const int lane = tid & 31, w = tid >> 5;       // w in 0..3
    const int r = lane >> 2, kc = lane & 3;
    const int qb = blockIdx.x, bh = blockIdx.y;
    const int b = bh >> 4, h = bh & 15;
    const int q0 = qb * 128;
    const size_t base = ((size_t)b * T_) * C_ + h * D_;

    // cp.async loader (128 threads): 64 rows x 16 float4-chunks = 1024 slots
    // = 128 threads x 8 iters. crow 0..7 (+8i), cc4 covers full row.
    const int crow = tid >> 4;             // 0..7
    const int cc4 = (tid & 15) * 4;        // 0..60
    auto issue = [&](int it) {
        const int s0 = it * 64;
        const int buf = it & 1;
        const uint32_t kd = sbase + (uint32_t)(QF + buf * KF + crow * LDQ + cc4) * 4;
        const uint32_t vd = sbase + (uint32_t)(QF + 2 * KF + buf * VF + crow * LDV + cc4) * 4;
        const float* ks = &k[base + (size_t)(s0 + crow) * C_ + cc4];
        const float* vs = &v[base + (size_t)(s0 + crow) * C_ + cc4];
#pragma unroll
        for (int i = 0; i < 8; i++) {
            CP_ASYNC16(kd + (uint32_t)(i * 8 * LDQ) * 4, ks + (size_t)i * 8 * C_);
            CP_ASYNC16(vd + (uint32_t)(i * 8 * LDV) * 4, vs + (size_t)i * 8 * C_);
        }
        CP_COMMIT();
    };

    issue(0);

    // Load Q tile (pre-rounded tf32; x0.125 exact). 2048 slots / 128 thr.
#pragma unroll
    for (int it = 0; it < 16; it++) {
        int f = tid + it * 128;
        int row = f >> 4, d4 = f & 15;
        float4 t = *reinterpret_cast<const float4*>(
            &q[base + (size_t)(q0 + row) * C_ + d4 * 4]);
        t.x *= 0.125f; t.y *= 0.125f; t.z *= 0.125f; t.w *= 0.125f;
        *reinterpret_cast<float4*>(&Qs[row * LDQ + d4 * 4]) = t;
    }

    float sc[2][8][4];
    float yacc[2][8][4];
#pragma unroll
    for (int mt = 0; mt < 2; mt++)
#pragma unroll
        for (int nt = 0; nt < 8; nt++)
#pragma unroll
            for (int j = 0; j < 4; j++) yacc[mt][nt][j] = 0.f;
    float mA[2] = {-1e30f, -1e30f}, mB[2] = {-1e30f, -1e30f};
    float lA[2] = {0.f, 0.f}, lB[2] = {0.f, 0.f};

    const int qrow0 = q0 + 32 * w;         // warp's first q row
    const int nit = 2 * qb + 2;
    for (int itk = 0; itk < nit; itk++) {
        const int s0 = itk * 64;
        CP_WAIT0();
        __syncthreads();
        if (itk + 1 < nit) issue(itk + 1);

        if (s0 <= qrow0 + 31) {
            const float* Kb = Ksb + (itk & 1) * KF;
            const float* Vb = Vsb + (itk & 1) * VF;

            // ---- S = Q K^T (register double-buffered over kk) ----
#pragma unroll
            for (int mt = 0; mt < 2; mt++)
#pragma unroll
                for (int nt = 0; nt < 8; nt++)
#pragma unroll
                    for (int j = 0; j < 4; j++) sc[mt][nt][j] = 0.f;

            uint2 qa01[2][2], qa23[2][2], kb[2][8];
#define QK_LOAD(kkv, bf)                                                     \
            {                                                                \
                const int ko = 8 * (kkv) + 2 * kc;                           \
                _Pragma("unroll")                                            \
                for (int mt = 0; mt < 2; mt++) {                             \
                    qa01[bf][mt] = *reinterpret_cast<const uint2*>(          \
                        &Qs[(32 * w + 16 * mt + r) * LDQ + ko]);             \
                    qa23[bf][mt] = *reinterpret_cast<const uint2*>(          \
                        &Qs[(32 * w + 16 * mt + r + 8) * LDQ + ko]);         \
                }                                                            \
                _Pragma("unroll")                                            \
                for (int nt = 0; nt < 8; nt++)                               \
                    kb[bf][nt] = *reinterpret_cast<const uint2*>(            \
                        &Kb[(8 * nt + r) * LDQ + ko]);                       \
            }
            QK_LOAD(0, 0)
#pragma unroll
            for (int kk = 0; kk < 8; kk++) {
                const int bf = kk & 1;
                if (kk < 7) QK_LOAD(kk + 1, bf ^ 1)
#pragma unroll
                for (int nt = 0; nt < 8; nt++)
#pragma unroll
                    for (int mt = 0; mt < 2; mt++)
                        mma_u(sc[mt][nt], qa01[bf][mt].x, qa23[bf][mt].x,
                              qa01[bf][mt].y, qa23[bf][mt].y,
                              kb[bf][nt].x, kb[bf][nt].y);
            }
#undef QK_LOAD

            // ---- causal mask (near diagonal only) ----
            if (s0 + 63 > qrow0) {
#pragma unroll
                for (int mt = 0; mt < 2; mt++) {
                    const int qA = qrow0 + 16 * mt + r, qB = qA + 8;
#pragma unroll
                    for (int nt = 0; nt < 8; nt++) {
                        int sg = s0 + 8 * nt + 2 * kc;
                        if (sg > qA)     sc[mt][nt][0] = -1e30f;
                        if (sg + 1 > qA) sc[mt][nt][1] = -1e30f;
                        if (sg > qB)     sc[mt][nt][2] = -1e30f;
                        if (sg + 1 > qB) sc[mt][nt][3] = -1e30f;
                    }
                }
            }

            // ---- online softmax per row-block mt ----
#pragma unroll
            for (int mt = 0; mt < 2; mt++) {
                float mxA = -1e30f, mxB = -1e30f;
#pragma unroll
                for (int nt = 0; nt < 8; nt++) {
                    mxA = fmaxf(mxA, fmaxf(sc[mt][nt][0], sc[mt][nt][1]));
                    mxB = fmaxf(mxB, fmaxf(sc[mt][nt][2], sc[mt][nt][3]));
                }
                mxA = fmaxf(mxA, __shfl_xor_sync(0xffffffffu, mxA, 1));
                mxA = fmaxf(mxA, __shfl_xor_sync(0xffffffffu, mxA, 2));
                mxB = fmaxf(mxB, __shfl_xor_sync(0xffffffffu, mxB, 1));
                mxB = fmaxf(mxB, __shfl_xor_sync(0xffffffffu, mxB, 2));
                float mnA = fmaxf(mA[mt], mxA), mnB = fmaxf(mB[mt], mxB);
                float cA = __expf(mA[mt] - mnA), cB = __expf(mB[mt] - mnB);
                mA[mt] = mnA; mB[mt] = mnB;
                float psA = 0.f, psB = 0.f;
#pragma unroll
                for (int nt = 0; nt < 8; nt++) {
                    float p0 = __expf(sc[mt][nt][0] - mnA);
                    float p1 = __expf(sc[mt][nt][1] - mnA);
                    float p2 = __expf(sc[mt][nt][2] - mnB);
                    float p3 = __expf(sc[mt][nt][3] - mnB);
                    psA += p0 + p1; psB += p2 + p3;
                    sc[mt][nt][0] = p0; sc[mt][nt][1] = p1;
                    sc[mt][nt][2] = p2; sc[mt][nt][3] = p3;
                }
                psA += __shfl_xor_sync(0xffffffffu, psA, 1);
                psA += __shfl_xor_sync(0xffffffffu, psA, 2);
                psB += __shfl_xor_sync(0xffffffffu, psB, 1);
                psB += __shfl_xor_sync(0xffffffffu, psB, 2);
                lA[mt] = lA[mt] * cA + psA;
                lB[mt] = lB[mt] * cB + psB;

#pragma unroll
                for (int nt = 0; nt < 8; nt++) {
                    yacc[mt][nt][0] *= cA; yacc[mt][nt][1] *= cA;
                    yacc[mt][nt][2] *= cB; yacc[mt][nt][3] *= cB;
                }
            }

            // ---- P to tf32 ----
#pragma unroll
            for (int mt = 0; mt < 2; mt++)
#pragma unroll
                for (int nt = 0; nt < 8; nt++)
#pragma unroll
                    for (int j = 0; j < 4; j++)
                        sc[mt][nt][j] = __uint_as_float(tf32r(sc[mt][nt][j]));

            // ---- y += P V (P in regs as A; V row-major as B; dbuf V) ----
            float vb0[2][8], vb1[2][8];
#define PV_LOAD(kkv, bf)                                                     \
            {                                                                \
                const float* v0p = &Vb[(8 * (kkv) + 2 * kc) * LDV + r];      \
                const float* v1p = v0p + LDV;                                \
                _Pragma("unroll")                                            \
                for (int nt = 0; nt < 8; nt++) {                             \
                    vb0[bf][nt] = v0p[8 * nt];                               \
                    vb1[bf][nt] = v1p[8 * nt];                               \
                }                                                            \
            }
            PV_LOAD(0, 0)
#pragma unroll
            for (int kk = 0; kk < 8; kk++) {
                const int bf = kk & 1;
                if (kk < 7) PV_LOAD(kk + 1, bf ^ 1)
#pragma unroll
                for (int mt = 0; mt < 2; mt++) {
                    uint32_t a0 = __float_as_uint(sc[mt][kk][0]);
                    uint32_t a1 = __float_as_uint(sc[mt][kk][2]);
                    uint32_t a2 = __float_as_uint(sc[mt][kk][1]);
                    uint32_t a3 = __float_as_uint(sc[mt][kk][3]);
#pragma unroll
                    for (int nt = 0; nt < 8; nt++)
                        mma_u(yacc[mt][nt], a0, a1, a2, a3,
                              __float_as_uint(vb0[bf][nt]),
                              __float_as_uint(vb1[bf][nt]));
                }
            }
#undef PV_LOAD
        }
    }

    // ---- epilogue: in-register normalize + rounded direct stores ----
#pragma unroll
    for (int mt = 0; mt < 2; mt++) {
        const float iA = 1.f / lA[mt], iB = 1.f / lB[mt];
        float* yA = &y[base + (size_t)(qrow0 + 16 * mt + r) * C_];
        float* yB = &y[base + (size_t)(qrow0 + 16 * mt + r + 8) * C_];
#pragma unroll
        for (int nt = 0; nt < 8; nt++) {
            const int cg = 8 * nt + 2 * kc;
            uint2 u0, u1;
            u0.x = tf32r(yacc[mt][nt][0] * iA);
            u0.y = tf32r(yacc[mt][nt][1] * iA);
            u1.x = tf32r(yacc[mt][nt][2] * iB);
            u1.y = tf32r(yacc[mt][nt][3] * iB);
            *reinterpret_cast<uint2*>(&yA[cg]) = u0;
            *reinterpret_cast<uint2*>(&yB[cg]) = u1;
        }
    }
}

// ---------------------------------------------------------------------------
// Launch
// ---------------------------------------------------------------------------
extern "C" void kernel_launch(void* const* d_in, const int* in_sizes, int n_in,
                              void* d_out, int out_size)
{
    const float* x  = (const float*)d_in[0];
    const float* wq = (const float*)d_in[1];
    const float* bq = (const float*)d_in[2];
    const float* wk = (const float*)d_in[3];
    const float* bk = (const float*)d_in[4];
    const float* wv = (const float*)d_in[5];
    const float* bv = (const float*)d_in[6];
    const float* wp = (const float*)d_in[7];
    const float* bp = (const float*)d_in[8];
    float* out = (float*)d_out;

    float *qp, *kp, *vp, *yp, *xp, *wr;
    cudaGetSymbolAddress((void**)&qp, g_q);
    cudaGetSymbolAddress((void**)&kp, g_k);
    cudaGetSymbolAddress((void**)&vp, g_v);
    cudaGetSymbolAddress((void**)&yp, g_y);
    cudaGetSymbolAddress((void**)&xp, g_x);
    cudaGetSymbolAddress((void**)&wr, g_w);

    cudaFuncSetAttribute(gemm_mma,
                         cudaFuncAttributeMaxDynamicSharedMemorySize, GEMM_SMEM);
    cudaFuncSetAttribute(attn_mma,
                         cudaFuncAttributeMaxDynamicSharedMemorySize, ATTN_SMEM3);

    // Pre-round x and weights to tf32 (RNA) once.
    const int RBLK = (M_ * C_ / 4 + 4 * C_ * C_ / 4) / 256;  // 12288
    round_tf32<<<RBLK, 256>>>(x, wq, wk, wv, wp, xp, wr);

    // Fused QKV projection; v (z==2) stored tf32-rounded.
    dim3 qkv_grid(C_ / 128, M_ / 256, 3);   // (8, 32, 3)
    gemm_mma<<<qkv_grid, 256, GEMM_SMEM>>>(xp, wr, bq, bk, bv, qp, kp, vp, 2);

    rope_kernel<<<(B_ * T_ * H_ * 32) / 256, 256>>>(qp, kp);

    dim3 agrid(16, 64);                     // q-tiles x (b*h)
    attn_mma<<<agrid, 128, ATTN_SMEM3>>>(qp, kp, vp, yp);

    // Output projection (z = 0 only, no rounding).
    dim3 proj_grid(C_ / 128, M_ / 256, 1);  // (8, 32, 1)
    gemm_mma<<<proj_grid, 256, GEMM_SMEM>>>(yp, wr + 3 * (size_t)C_ * C_,
                                            bp, bp, bp, out, out, out, -1);
}